// round 10
// baseline (speedup 1.0000x reference)
#include <cuda_runtime.h>

#define BS_  8192
#define NS_  30
#define KH_  14      // each side eliminates 14 blocks; interface blocks 14,15
#define E_   64      // elements per block
#define TPB  64      // threads 0-31: top halves (2 elems each), 32-63: bottom
#define PE   2       // elements per thread

#define SV_F 18
#define SV_BYTES (SV_F * KH_ * PE * TPB * 4)   // 129024 B

// conflict-free smem record access
#define SV(pe, step, f) s_sv[(((step)*SV_F + (f))*PE + (pe)) * TPB + tid]

// One block-elimination step for element lane `pe`.
#define ELIM_STEP(pe, SVIDX) do {                                                \
    float il00 = rsqrtf(D000[pe]);                                               \
    float l10 = D010[pe]*il00, l20 = D020[pe]*il00;                              \
    float il11 = rsqrtf(D011[pe] - l10*l10);                                     \
    float l21 = (D021[pe] - l20*l10)*il11;                                       \
    float il22 = rsqrtf(D022[pe] - l20*l20 - l21*l21);                           \
    float w0,w1,w2;                                                              \
    w0 = A00[pe]*il00; w1 = (A01[pe] - w0*l10)*il11;                             \
    w2 = (A02[pe] - w0*l20 - w1*l21)*il22;                                       \
    A00[pe]=w0; A01[pe]=w1; A02[pe]=w2;                                          \
    w0 = A10[pe]*il00; w1 = (A11[pe] - w0*l10)*il11;                             \
    w2 = (A12[pe] - w0*l20 - w1*l21)*il22;                                       \
    A10[pe]=w0; A11[pe]=w1; A12[pe]=w2;                                          \
    w0 = A20[pe]*il00; w1 = (A21[pe] - w0*l10)*il11;                             \
    w2 = (A22[pe] - w0*l20 - w1*l21)*il22;                                       \
    A20[pe]=w0; A21[pe]=w1; A22[pe]=w2;                                          \
    float m1 = -il11;                                                            \
    float m2 = il11*l21*il22;                                                    \
    float y0 = r00[pe]*il00;                                                     \
    float y1 = (r01[pe] - y0*l10)*il11;                                          \
    float y2 = (r02[pe] - y0*l20 - y1*l21)*il22;                                 \
    r10[pe] -= A00[pe]*y0 + A01[pe]*y1 + A02[pe]*y2;                             \
    r11[pe] -= A10[pe]*y0 + A11[pe]*y1 + A12[pe]*y2;                             \
    r12[pe] -= A20[pe]*y0 + A21[pe]*y1 + A22[pe]*y2;                             \
    r21[pe] -= m1*y1 + m2*y2;                                                    \
    D100[pe] -= A00[pe]*A00[pe] + A01[pe]*A01[pe] + A02[pe]*A02[pe];             \
    D110[pe] -= A10[pe]*A00[pe] + A11[pe]*A01[pe] + A12[pe]*A02[pe];             \
    D120[pe] -= A20[pe]*A00[pe] + A21[pe]*A01[pe] + A22[pe]*A02[pe];             \
    D111[pe] -= A10[pe]*A10[pe] + A11[pe]*A11[pe] + A12[pe]*A12[pe];             \
    D121[pe] -= A20[pe]*A10[pe] + A21[pe]*A11[pe] + A22[pe]*A12[pe];             \
    D122[pe] -= A20[pe]*A20[pe] + A21[pe]*A21[pe] + A22[pe]*A22[pe];             \
    B10[pe] -= m1*A01[pe] + m2*A02[pe];                                          \
    B11[pe] -= m1*A11[pe] + m2*A12[pe];                                          \
    B12[pe] -= m1*A21[pe] + m2*A22[pe];                                          \
    D211[pe] -= m1*m1 + m2*m2;                                                   \
    SV(pe,SVIDX, 0)=il00; SV(pe,SVIDX, 1)=l10;  SV(pe,SVIDX, 2)=l20;             \
    SV(pe,SVIDX, 3)=il11; SV(pe,SVIDX, 4)=l21;  SV(pe,SVIDX, 5)=il22;            \
    SV(pe,SVIDX, 6)=A00[pe]; SV(pe,SVIDX, 7)=A01[pe]; SV(pe,SVIDX, 8)=A02[pe];   \
    SV(pe,SVIDX, 9)=A10[pe]; SV(pe,SVIDX,10)=A11[pe]; SV(pe,SVIDX,11)=A12[pe];   \
    SV(pe,SVIDX,12)=A20[pe]; SV(pe,SVIDX,13)=A21[pe]; SV(pe,SVIDX,14)=A22[pe];   \
    SV(pe,SVIDX,15)=y0;   SV(pe,SVIDX,16)=y1;   SV(pe,SVIDX,17)=y2;              \
    D000[pe]=D100[pe]; D010[pe]=D110[pe]; D020[pe]=D120[pe];                     \
    D011[pe]=D111[pe]; D021[pe]=D121[pe]; D022[pe]=D122[pe];                     \
    D100[pe]=0; D110[pe]=0; D120[pe]=0; D111[pe]=D211[pe];                       \
    D121[pe]=0; D122[pe]=0; D211[pe]=0;                                          \
    A00[pe]=0; A01[pe]=0; A02[pe]=0;                                             \
    A10[pe]=B10[pe]; A11[pe]=B11[pe]; A12[pe]=B12[pe];                           \
    A20[pe]=0; A21[pe]=0; A22[pe]=0;                                             \
    B10[pe]=0; B11[pe]=0; B12[pe]=0;                                             \
    r00[pe]=r10[pe]; r01[pe]=r11[pe]; r02[pe]=r12[pe];                           \
    r10[pe]=0; r11[pe]=r21[pe]; r12[pe]=0; r21[pe]=0;                            \
} while(0)

__global__ __launch_bounds__(TPB)
void ode_babe2_kernel(const float* __restrict__ coeffs,
                      const float* __restrict__ rhs,
                      const float* __restrict__ ivr,
                      const float* __restrict__ steps,
                      float* __restrict__ out)
{
    __shared__ float s_co[E_ * 90];
    __shared__ float s_rr[E_ * 30];
    __shared__ float s_st[E_ * 29];
    __shared__ float s_iv[E_ * 4];
    __shared__ float s_ex[E_ * 2 * 16];
    extern __shared__ float s_sv[];

    const int tid = threadIdx.x;
    const size_t blk = (size_t)blockIdx.x * E_;

    // ---- coalesced staging ----
    {
        const float4* g = (const float4*)(coeffs + blk * 90);
        float4* s = (float4*)s_co;
        for (int k = tid; k < E_*90/4; k += TPB) s[k] = g[k];
    }
    {
        const float4* g = (const float4*)(rhs + blk * 30);
        float4* s = (float4*)s_rr;
        for (int k = tid; k < E_*30/4; k += TPB) s[k] = g[k];
    }
    {
        const float4* g = (const float4*)(steps + blk * 29);
        float4* s = (float4*)s_st;
        for (int k = tid; k < E_*29/4; k += TPB) s[k] = g[k];
    }
    {
        const float4* g = (const float4*)(ivr + blk * 4);
        float4* s = (float4*)s_iv;
        for (int k = tid; k < E_*4/4; k += TPB) s[k] = g[k];
    }
    __syncthreads();

    const int  u   = tid & 31;        // element-pair index
    const bool top = tid < 32;

    const float* cc [PE] = { s_co + (2*u+0)*90, s_co + (2*u+1)*90 };
    const float* rrp[PE] = { s_rr + (2*u+0)*30, s_rr + (2*u+1)*30 };
    const float* stp[PE] = { s_st + (2*u+0)*29, s_st + (2*u+1)*29 };

    const float sgn   = top ? 1.f : -1.f;
    const int   cbase = top ? 0 : 87;
    const int   cstep = top ? 3 : -3;
    const int   rbase = top ? 0 : 29;
    const int   rstep = top ? 1 : -1;
    const int   hbase = top ? 0 : 28;
    const int   hstep = top ? 1 : -1;
    const float one_t = top ? 1.f : 0.f;

    float iva0[PE], iva1[PE], iva2[PE], iva3[PE];
    #pragma unroll
    for (int pe = 0; pe < PE; pe++) {
        int e = 2*u + pe;
        iva0[pe] = top ? s_iv[e*4+0] : 0.f;
        iva1[pe] = top ? s_iv[e*4+1] : 0.f;
        iva2[pe] = top ? s_iv[e*4+2] : 0.f;
        iva3[pe] = top ? s_iv[e*4+3] : 0.f;
    }

    float D000[PE]={0,0},D010[PE]={0,0},D020[PE]={0,0},
          D011[PE]={0,0},D021[PE]={0,0},D022[PE]={0,0};
    float D100[PE]={0,0},D110[PE]={0,0},D120[PE]={0,0},
          D111[PE]={0,0},D121[PE]={0,0},D122[PE]={0,0};
    float D211[PE]={0,0};
    float A00[PE]={0,0},A01[PE]={0,0},A02[PE]={0,0},
          A10[PE]={0,0},A11[PE]={0,0},A12[PE]={0,0},
          A20[PE]={0,0},A21[PE]={0,0},A22[PE]={0,0};
    float B10[PE]={0,0},B11[PE]={0,0},B12[PE]={0,0};
    float r00[PE]={0,0},r01[PE]={0,0},r02[PE]={0,0},
          r10[PE]={0,0},r11[PE]={0,0},r12[PE]={0,0},r21[PE]={0,0};

    #pragma unroll
    for (int s = 0; s < KH_; s++) {
        #pragma unroll
        for (int pe = 0; pe < PE; pe++) {
            const float* cb = cc[pe] + cbase + cstep*s;
            float c0=cb[0], c1=cb[1], c2=cb[2];
            float rv = rrp[pe][rbase + rstep*s];

            D000[pe] += c0*c0; D010[pe] += c1*c0; D020[pe] += c2*c0;
            D011[pe] += c1*c1; D021[pe] += c2*c1; D022[pe] += c2*c2;
            r00[pe] += c0*rv; r01[pe] += c1*rv; r02[pe] += c2*rv;
            if (s == 0) { D000[pe] += one_t; D011[pe] += one_t;
                          r00[pe] += iva0[pe]; r01[pe] += iva1[pe]; }
            if (s == 1) { D000[pe] += one_t; D011[pe] += one_t;
                          r00[pe] += iva2[pe]; r01[pe] += iva3[pe]; }

            float h = sgn * stp[pe][hbase + hstep*s];
            float h2 = h*h, h3 = h2*h, h4 = h2*h2;
            D000[pe] += 2.f;       D010[pe] += h;          D020[pe] += 0.5f*h2;
            D011[pe] += 3.f*h2;    D021[pe] += 1.5f*h3;    D022[pe] += 1.25f*h4;
            A00[pe]  += -2.f;      A01[pe]  += -h;         A02[pe]  += -0.5f*h2;
            A10[pe]  += h;         A11[pe]  += -2.f*h2;    A12[pe]  += -h3;
            A20[pe]  += -0.5f*h2;  A21[pe]  += h3;
            D100[pe] += 2.f;       D110[pe] += -h;         D120[pe] += 0.5f*h2;
            D111[pe] += 3.f*h2;    D121[pe] += -1.5f*h3;   D122[pe] += 1.25f*h4;

            float cp = h + sgn * stp[pe][hbase + hstep*(s+1)];
            D011[pe] += 1.f;  A21[pe] += cp;
            D122[pe] += cp*cp; B12[pe] += -cp; D211[pe] += 1.f;

            ELIM_STEP(pe, s);
        }
    }

    // ---- export window carries ----
    #pragma unroll
    for (int pe = 0; pe < PE; pe++) {
        int e = 2*u + pe;
        float* ex = s_ex + (e*2 + (top ? 0 : 1)) * 16;
        ex[0]=D000[pe]; ex[1]=D010[pe]; ex[2]=D020[pe];
        ex[3]=D011[pe]; ex[4]=D021[pe]; ex[5]=D022[pe];
        ex[6]=D111[pe];
        ex[7]=A10[pe]; ex[8]=A11[pe]; ex[9]=A12[pe];
        ex[10]=r00[pe]; ex[11]=r01[pe]; ex[12]=r02[pe];
        ex[13]=r11[pe];
    }
    __syncthreads();

    // ---- interface: 6x6 SPD solve for x_14, x_15 (per element) ----
    float X0[PE], X1[PE], X2[PE], X3[PE], X4[PE], X5[PE];
    #pragma unroll
    for (int pe = 0; pe < PE; pe++) {
        int e = 2*u + pe;
        const float* te = s_ex + (e*2 + 0) * 16;
        const float* be = s_ex + (e*2 + 1) * 16;
        float h = stp[pe][KH_];
        float h2 = h*h, h3 = h2*h, h4 = h2*h2;
        float cK0=cc[pe][3*KH_], cK1=cc[pe][3*KH_+1], cK2=cc[pe][3*KH_+2];
        float cL0=cc[pe][3*KH_+3], cL1=cc[pe][3*KH_+4], cL2=cc[pe][3*KH_+5];
        float rvK = rrp[pe][KH_], rvL = rrp[pe][KH_+1];

        float d00 = te[0] + cK0*cK0 + 2.f;
        float d10 = te[1] + cK1*cK0 + h;
        float d20 = te[2] + cK2*cK0 + 0.5f*h2;
        float d11 = te[3] + cK1*cK1 + 3.f*h2 + be[6];
        float d21 = te[4] + cK2*cK1 + 1.5f*h3;
        float d22 = te[5] + cK2*cK2 + 1.25f*h4;
        float e00 = be[0] + cL0*cL0 + 2.f;
        float e10 = be[1] + cL1*cL0 - h;
        float e20 = be[2] + cL2*cL0 + 0.5f*h2;
        float e11 = be[3] + cL1*cL1 + 3.f*h2 + te[6];
        float e21 = be[4] + cL2*cL1 - 1.5f*h3;
        float e22 = be[5] + cL2*cL2 + 1.25f*h4;
        float a00 = -2.f;
        float a01 = -h        + be[7];
        float a02 = -0.5f*h2;
        float a10 =  h        + te[7];
        float a11 = -2.f*h2   + te[8] + be[8];
        float a12 = -h3       + te[9];
        float a20 = -0.5f*h2;
        float a21 =  h3       + be[9];
        float a22 = 0.f;
        float rk0 = te[10] + cK0*rvK;
        float rk1 = te[11] + cK1*rvK + be[13];
        float rk2 = te[12] + cK2*rvK;
        float rl0 = be[10] + cL0*rvL;
        float rl1 = be[11] + cL1*rvL + te[13];
        float rl2 = be[12] + cL2*rvL;

        float il00 = rsqrtf(d00);
        float l10 = d10*il00, l20 = d20*il00;
        float il11 = rsqrtf(d11 - l10*l10);
        float l21 = (d21 - l20*l10)*il11;
        float il22 = rsqrtf(d22 - l20*l20 - l21*l21);
        float w00 = a00*il00, w01 = (a01 - w00*l10)*il11, w02 = (a02 - w00*l20 - w01*l21)*il22;
        float w10 = a10*il00, w11 = (a11 - w10*l10)*il11, w12 = (a12 - w10*l20 - w11*l21)*il22;
        float w20 = a20*il00, w21 = (a21 - w20*l10)*il11, w22 = (a22 - w20*l20 - w21*l21)*il22;
        float s00 = e00 - (w00*w00 + w01*w01 + w02*w02);
        float s10 = e10 - (w10*w00 + w11*w01 + w12*w02);
        float s20 = e20 - (w20*w00 + w21*w01 + w22*w02);
        float s11 = e11 - (w10*w10 + w11*w11 + w12*w12);
        float s21 = e21 - (w20*w10 + w21*w11 + w22*w12);
        float s22 = e22 - (w20*w20 + w21*w21 + w22*w22);
        float jl00 = rsqrtf(s00);
        float k10 = s10*jl00, k20 = s20*jl00;
        float jl11 = rsqrtf(s11 - k10*k10);
        float k21 = (s21 - k20*k10)*jl11;
        float jl22 = rsqrtf(s22 - k20*k20 - k21*k21);
        float y10 = rk0*il00;
        float y11 = (rk1 - y10*l10)*il11;
        float y12 = (rk2 - y10*l20 - y11*l21)*il22;
        float t0 = rl0 - (w00*y10 + w01*y11 + w02*y12);
        float t1 = rl1 - (w10*y10 + w11*y11 + w12*y12);
        float t2 = rl2 - (w20*y10 + w21*y11 + w22*y12);
        float y20 = t0*jl00;
        float y21 = (t1 - y20*k10)*jl11;
        float y22 = (t2 - y20*k20 - y21*k21)*jl22;
        float x25 = y22*jl22;
        float x24 = (y21 - k21*x25)*jl11;
        float x23 = (y20 - k10*x24 - k20*x25)*jl00;
        float z0 = y10 - (w00*x23 + w10*x24 + w20*x25);
        float z1 = y11 - (w01*x23 + w11*x24 + w21*x25);
        float z2 = y12 - (w02*x23 + w12*x24 + w22*x25);
        float x22_ = z2*il22;
        float x21_ = (z1 - l21*x22_)*il11;
        float x20_ = (z0 - l10*x21_ - l20*x22_)*il00;
        X0[pe]=x20_; X1[pe]=x21_; X2[pe]=x22_; X3[pe]=x23; X4[pe]=x24; X5[pe]=x25;
    }

    // ---- back substitution (both elements interleaved) ----
    float xn0[PE], xn1[PE], xn2[PE], xp1[PE];
    #pragma unroll
    for (int pe = 0; pe < PE; pe++) {
        float* ox = s_co + (2*u+pe) * 90;
        if (top) {
            ox[3*KH_+0]=X0[pe]; ox[3*KH_+1]=X1[pe]; ox[3*KH_+2]=X2[pe];
            ox[3*KH_+3]=X3[pe]; ox[3*KH_+4]=X4[pe]; ox[3*KH_+5]=X5[pe];
        }
        xn0[pe] = top ? X0[pe] : X3[pe];
        xn1[pe] = top ? X1[pe] : X4[pe];
        xn2[pe] = top ? X2[pe] : X5[pe];
        xp1[pe] = top ? X4[pe] : X1[pe];
    }
    const int obase = top ? 0 : 87;
    const int ostep = top ? 3 : -3;

    #pragma unroll
    for (int k = KH_-1; k >= 0; k--) {
        #pragma unroll
        for (int pe = 0; pe < PE; pe++) {
            float q0=SV(pe,k,0), q1=SV(pe,k,1), q2=SV(pe,k,2),
                  q3=SV(pe,k,3), q4=SV(pe,k,4), q5=SV(pe,k,5);
            float a00=SV(pe,k,6), a01=SV(pe,k,7), a02=SV(pe,k,8);
            float a10=SV(pe,k,9), a11=SV(pe,k,10), a12=SV(pe,k,11);
            float a20=SV(pe,k,12), a21=SV(pe,k,13), a22=SV(pe,k,14);
            float y0=SV(pe,k,15), y1=SV(pe,k,16), y2=SV(pe,k,17);
            float m2 = q3*q4*q5;
            float u0 = y0 - (a00*xn0[pe] + a10*xn1[pe] + a20*xn2[pe]);
            float u1 = y1 - (a01*xn0[pe] + a11*xn1[pe] + a21*xn2[pe]) + q3*xp1[pe];
            float u2 = y2 - (a02*xn0[pe] + a12*xn1[pe] + a22*xn2[pe]) - m2*xp1[pe];
            float x2 = u2*q5;
            float x1 = (u1 - q4*x2)*q3;
            float x0 = (u0 - q1*x1 - q2*x2)*q0;
            float* op = s_co + (2*u+pe)*90 + obase + ostep*k;
            op[0] = x0; op[1] = x1; op[2] = x2;
            xp1[pe] = xn1[pe]; xn0[pe] = x0; xn1[pe] = x1; xn2[pe] = x2;
        }
    }

    // ---- coalesced store-out ----
    __syncthreads();
    {
        const float4* s = (const float4*)s_co;
        float4* g = (float4*)(out + blk * 90);
        for (int k = tid; k < E_*90/4; k += TPB) g[k] = s[k];
    }
}

extern "C" void kernel_launch(void* const* d_in, const int* in_sizes, int n_in,
                              void* d_out, int out_size) {
    const float* coeffs = (const float*)d_in[0];
    const float* rhs    = (const float*)d_in[1];
    const float* iv_rhs = (const float*)d_in[2];
    const float* steps  = (const float*)d_in[3];
    float* out = (float*)d_out;

    cudaFuncSetAttribute(ode_babe2_kernel,
                         cudaFuncAttributeMaxDynamicSharedMemorySize, SV_BYTES);

    dim3 block(TPB);
    dim3 grid(BS_ / E_);
    ode_babe2_kernel<<<grid, block, SV_BYTES>>>(coeffs, rhs, iv_rhs, steps, out);
}

// round 11
// speedup vs baseline: 1.4276x; 1.4276x over previous
#include <cuda_runtime.h>

#define BS_  8192
#define NS_  30
#define KH_  14      // each side eliminates 14 blocks; interface blocks 14,15
#define E_   32      // elements per block
#define TPB  64      // lane 2k = top half of elem k, lane 2k+1 = bottom half

#define SV_F 18
#define SV_BYTES (SV_F * KH_ * TPB * 4)   // 64512 B dynamic smem

// conflict-free smem record access: consecutive tids -> consecutive banks
#define SV(step, f) s_sv[((step)*SV_F + (f)) * TPB + tid]

// Streaming block elimination step; factor record -> shared memory.
#define ELIM_STEP(SVIDX) do {                                                    \
    float il00 = rsqrtf(D000);                                                   \
    float l10 = D010*il00, l20 = D020*il00;                                      \
    float il11 = rsqrtf(D011 - l10*l10);                                         \
    float l21 = (D021 - l20*l10)*il11;                                           \
    float il22 = rsqrtf(D022 - l20*l20 - l21*l21);                               \
    float w0,w1,w2;                                                              \
    w0 = A00*il00; w1 = (A01 - w0*l10)*il11; w2 = (A02 - w0*l20 - w1*l21)*il22;  \
    A00=w0; A01=w1; A02=w2;                                                      \
    w0 = A10*il00; w1 = (A11 - w0*l10)*il11; w2 = (A12 - w0*l20 - w1*l21)*il22;  \
    A10=w0; A11=w1; A12=w2;                                                      \
    w0 = A20*il00; w1 = (A21 - w0*l10)*il11; w2 = (A22 - w0*l20 - w1*l21)*il22;  \
    A20=w0; A21=w1; A22=w2;                                                      \
    float m1 = -il11;                                                            \
    float m2 = il11*l21*il22;                                                    \
    float y0 = r00*il00;                                                         \
    float y1 = (r01 - y0*l10)*il11;                                              \
    float y2 = (r02 - y0*l20 - y1*l21)*il22;                                     \
    r10 -= A00*y0 + A01*y1 + A02*y2;                                             \
    r11 -= A10*y0 + A11*y1 + A12*y2;                                             \
    r12 -= A20*y0 + A21*y1 + A22*y2;                                             \
    r21 -= m1*y1 + m2*y2;                                                        \
    D100 -= A00*A00 + A01*A01 + A02*A02;                                         \
    D110 -= A10*A00 + A11*A01 + A12*A02;                                         \
    D120 -= A20*A00 + A21*A01 + A22*A02;                                         \
    D111 -= A10*A10 + A11*A11 + A12*A12;                                         \
    D121 -= A20*A10 + A21*A11 + A22*A12;                                         \
    D122 -= A20*A20 + A21*A21 + A22*A22;                                         \
    B10 -= m1*A01 + m2*A02;                                                      \
    B11 -= m1*A11 + m2*A12;                                                      \
    B12 -= m1*A21 + m2*A22;                                                      \
    D211 -= m1*m1 + m2*m2;                                                       \
    SV(SVIDX, 0)=il00; SV(SVIDX, 1)=l10;  SV(SVIDX, 2)=l20;                      \
    SV(SVIDX, 3)=il11; SV(SVIDX, 4)=l21;  SV(SVIDX, 5)=il22;                     \
    SV(SVIDX, 6)=A00;  SV(SVIDX, 7)=A01;  SV(SVIDX, 8)=A02;                      \
    SV(SVIDX, 9)=A10;  SV(SVIDX,10)=A11;  SV(SVIDX,11)=A12;                      \
    SV(SVIDX,12)=A20;  SV(SVIDX,13)=A21;  SV(SVIDX,14)=A22;                      \
    SV(SVIDX,15)=y0;   SV(SVIDX,16)=y1;   SV(SVIDX,17)=y2;                       \
    D000=D100; D010=D110; D020=D120; D011=D111; D021=D121; D022=D122;            \
    D100=0; D110=0; D120=0; D111=D211; D121=0; D122=0; D211=0;                   \
    A00=0; A01=0; A02=0; A10=B10; A11=B11; A12=B12; A20=0; A21=0; A22=0;         \
    B10=0; B11=0; B12=0;                                                         \
    r00=r10; r01=r11; r02=r12;                                                   \
    r10=0; r11=r21; r12=0; r21=0;                                                \
} while(0)

__global__ __launch_bounds__(TPB)
void ode_babe_kernel(const float* __restrict__ coeffs,
                     const float* __restrict__ rhs,
                     const float* __restrict__ ivr,
                     const float* __restrict__ steps,
                     float* __restrict__ out)
{
    __shared__ float s_co[E_ * 90];   // coeffs in; reused for x out
    __shared__ float s_rr[E_ * 30];
    __shared__ float s_st[E_ * 29];
    __shared__ float s_iv[E_ * 4];
    extern __shared__ float s_sv[];   // factor records (dynamic)

    const int tid = threadIdx.x;
    const size_t blk = (size_t)blockIdx.x * E_;

    // ---- coalesced staging ----
    {
        const float4* g = (const float4*)(coeffs + blk * 90);
        float4* s = (float4*)s_co;
        for (int k = tid; k < E_*90/4; k += TPB) s[k] = g[k];
    }
    {
        const float4* g = (const float4*)(rhs + blk * 30);
        float4* s = (float4*)s_rr;
        for (int k = tid; k < E_*30/4; k += TPB) s[k] = g[k];
    }
    {
        const float4* g = (const float4*)(steps + blk * 29);
        float4* s = (float4*)s_st;
        for (int k = tid; k < E_*29/4; k += TPB) s[k] = g[k];
    }
    {
        const float4* g = (const float4*)(ivr + blk * 4);
        float4* s = (float4*)s_iv;
        for (int k = tid; k < E_*4/4; k += TPB) s[k] = g[k];
    }
    __syncthreads();

    const int  e   = tid >> 1;          // element index within block
    const bool top = (tid & 1) == 0;    // even lane = top, odd = bottom

    const float* cc  = s_co + e * 90;
    const float* rrp = s_rr + e * 30;
    const float* stp = s_st + e * 29;

    // direction constants (uniform code path)
    const float sgn   = top ? 1.f : -1.f;
    const int   cbase = top ? 0 : 87;
    const int   cstep = top ? 3 : -3;
    const int   rbase = top ? 0 : 29;
    const int   rstep = top ? 1 : -1;
    const int   hbase = top ? 0 : 28;
    const int   hstep = top ? 1 : -1;

    const float one_t = top ? 1.f : 0.f;
    const float iva0 = top ? s_iv[e*4+0] : 0.f;
    const float iva1 = top ? s_iv[e*4+1] : 0.f;
    const float iva2 = top ? s_iv[e*4+2] : 0.f;
    const float iva3 = top ? s_iv[e*4+3] : 0.f;

    float D000=0,D010=0,D020=0,D011=0,D021=0,D022=0;
    float D100=0,D110=0,D120=0,D111=0,D121=0,D122=0;
    float D211=0;
    float A00=0,A01=0,A02=0,A10=0,A11=0,A12=0,A20=0,A21=0,A22=0;
    float B10=0,B11=0,B12=0;
    float r00=0,r01=0,r02=0, r10=0,r11=0,r12=0, r21=0;

    #pragma unroll
    for (int s = 0; s < KH_; s++) {
        const float* cb = cc + cbase + cstep*s;
        float c0=cb[0], c1=cb[1], c2=cb[2];
        float rv = rrp[rbase + rstep*s];

        D000 += c0*c0; D010 += c1*c0; D020 += c2*c0;
        D011 += c1*c1; D021 += c2*c1; D022 += c2*c2;
        r00 += c0*rv; r01 += c1*rv; r02 += c2*rv;
        if (s == 0) { D000 += one_t; D011 += one_t; r00 += iva0; r01 += iva1; }
        if (s == 1) { D000 += one_t; D011 += one_t; r00 += iva2; r01 += iva3; }

        float h = sgn * stp[hbase + hstep*s];
        float h2 = h*h, h3 = h2*h, h4 = h2*h2;
        D000 += 2.f;       D010 += h;          D020 += 0.5f*h2;
        D011 += 3.f*h2;    D021 += 1.5f*h3;    D022 += 1.25f*h4;
        A00  += -2.f;      A01  += -h;         A02  += -0.5f*h2;
        A10  += h;         A11  += -2.f*h2;    A12  += -h3;
        A20  += -0.5f*h2;  A21  += h3;
        D100 += 2.f;       D110 += -h;         D120 += 0.5f*h2;
        D111 += 3.f*h2;    D121 += -1.5f*h3;   D122 += 1.25f*h4;

        float cp = h + sgn * stp[hbase + hstep*(s+1)];
        D011 += 1.f;  A21 += cp;
        D122 += cp*cp; B12 += -cp; D211 += 1.f;

        ELIM_STEP(s);
    }

    // ---- interface carry exchange via warp shuffle (partner = lane^1) ----
    float te[14], be[14];
    {
        float mine[14] = { D000, D010, D020, D011, D021, D022, D111,
                           A10, A11, A12, r00, r01, r02, r11 };
        #pragma unroll
        for (int i = 0; i < 14; i++) {
            float theirs = __shfl_xor_sync(0xffffffffu, mine[i], 1);
            te[i] = top ? mine[i] : theirs;
            be[i] = top ? theirs  : mine[i];
        }
    }

    // ---- interface: 6x6 SPD solve for x_14, x_15 (computed by both lanes) ----
    float x10_, x11_, x12_, x20_, x21_, x22_;
    {
        float h = stp[KH_];
        float h2 = h*h, h3 = h2*h, h4 = h2*h2;
        float cK0=cc[3*KH_], cK1=cc[3*KH_+1], cK2=cc[3*KH_+2];
        float cL0=cc[3*KH_+3], cL1=cc[3*KH_+4], cL2=cc[3*KH_+5];
        float rvK = rrp[KH_], rvL = rrp[KH_+1];

        float d00 = te[0] + cK0*cK0 + 2.f;
        float d10 = te[1] + cK1*cK0 + h;
        float d20 = te[2] + cK2*cK0 + 0.5f*h2;
        float d11 = te[3] + cK1*cK1 + 3.f*h2 + be[6];
        float d21 = te[4] + cK2*cK1 + 1.5f*h3;
        float d22 = te[5] + cK2*cK2 + 1.25f*h4;
        float e00 = be[0] + cL0*cL0 + 2.f;
        float e10 = be[1] + cL1*cL0 - h;
        float e20 = be[2] + cL2*cL0 + 0.5f*h2;
        float e11 = be[3] + cL1*cL1 + 3.f*h2 + te[6];
        float e21 = be[4] + cL2*cL1 - 1.5f*h3;
        float e22 = be[5] + cL2*cL2 + 1.25f*h4;
        float a00 = -2.f;
        float a01 = -h        + be[7];
        float a02 = -0.5f*h2;
        float a10 =  h        + te[7];
        float a11 = -2.f*h2   + te[8] + be[8];
        float a12 = -h3       + te[9];
        float a20 = -0.5f*h2;
        float a21 =  h3       + be[9];
        float a22 = 0.f;
        float rk0 = te[10] + cK0*rvK;
        float rk1 = te[11] + cK1*rvK + be[13];
        float rk2 = te[12] + cK2*rvK;
        float rl0 = be[10] + cL0*rvL;
        float rl1 = be[11] + cL1*rvL + te[13];
        float rl2 = be[12] + cL2*rvL;

        float il00 = rsqrtf(d00);
        float l10 = d10*il00, l20 = d20*il00;
        float il11 = rsqrtf(d11 - l10*l10);
        float l21 = (d21 - l20*l10)*il11;
        float il22 = rsqrtf(d22 - l20*l20 - l21*l21);
        float w00 = a00*il00, w01 = (a01 - w00*l10)*il11, w02 = (a02 - w00*l20 - w01*l21)*il22;
        float w10 = a10*il00, w11 = (a11 - w10*l10)*il11, w12 = (a12 - w10*l20 - w11*l21)*il22;
        float w20 = a20*il00, w21 = (a21 - w20*l10)*il11, w22 = (a22 - w20*l20 - w21*l21)*il22;
        float s00 = e00 - (w00*w00 + w01*w01 + w02*w02);
        float s10 = e10 - (w10*w00 + w11*w01 + w12*w02);
        float s20 = e20 - (w20*w00 + w21*w01 + w22*w02);
        float s11 = e11 - (w10*w10 + w11*w11 + w12*w12);
        float s21 = e21 - (w20*w10 + w21*w11 + w22*w12);
        float s22 = e22 - (w20*w20 + w21*w21 + w22*w22);
        float jl00 = rsqrtf(s00);
        float k10 = s10*jl00, k20 = s20*jl00;
        float jl11 = rsqrtf(s11 - k10*k10);
        float k21 = (s21 - k20*k10)*jl11;
        float jl22 = rsqrtf(s22 - k20*k20 - k21*k21);
        float y10 = rk0*il00;
        float y11 = (rk1 - y10*l10)*il11;
        float y12 = (rk2 - y10*l20 - y11*l21)*il22;
        float t0 = rl0 - (w00*y10 + w01*y11 + w02*y12);
        float t1 = rl1 - (w10*y10 + w11*y11 + w12*y12);
        float t2 = rl2 - (w20*y10 + w21*y11 + w22*y12);
        float y20 = t0*jl00;
        float y21 = (t1 - y20*k10)*jl11;
        float y22 = (t2 - y20*k20 - y21*k21)*jl22;
        x22_ = y22*jl22;
        x21_ = (y21 - k21*x22_)*jl11;
        x20_ = (y20 - k10*x21_ - k20*x22_)*jl00;
        float z0 = y10 - (w00*x20_ + w10*x21_ + w20*x22_);
        float z1 = y11 - (w01*x20_ + w11*x21_ + w21*x22_);
        float z2 = y12 - (w02*x20_ + w12*x21_ + w22*x22_);
        x12_ = z2*il22;
        x11_ = (z1 - l21*x12_)*il11;
        x10_ = (z0 - l10*x11_ - l20*x12_)*il00;
    }

    // ---- back substitution (uniform path, prefetched smem factor reads) ----
    float* ox = s_co + e * 90;   // coeffs consumed; reuse as output staging
    if (top) {
        ox[3*KH_+0]=x10_; ox[3*KH_+1]=x11_; ox[3*KH_+2]=x12_;
        ox[3*KH_+3]=x20_; ox[3*KH_+4]=x21_; ox[3*KH_+5]=x22_;
    }
    float xn0 = top ? x10_ : x20_;
    float xn1 = top ? x11_ : x21_;
    float xn2 = top ? x12_ : x22_;
    float xp1 = top ? x21_ : x11_;
    const int obase = top ? 0 : 87;
    const int ostep = top ? 3 : -3;

    float pv[SV_F];
    #pragma unroll
    for (int f = 0; f < SV_F; f++) pv[f] = SV(KH_-1, f);

    #pragma unroll
    for (int k = KH_-1; k >= 0; k--) {
        float q[SV_F];
        #pragma unroll
        for (int f = 0; f < SV_F; f++) q[f] = pv[f];
        if (k > 0) {
            #pragma unroll
            for (int f = 0; f < SV_F; f++) pv[f] = SV(k-1, f);
        }
        float m2 = q[3]*q[4]*q[5];
        float u0 = q[15] - (q[6]*xn0 + q[ 9]*xn1 + q[12]*xn2);
        float u1 = q[16] - (q[7]*xn0 + q[10]*xn1 + q[13]*xn2) + q[3]*xp1;
        float u2 = q[17] - (q[8]*xn0 + q[11]*xn1 + q[14]*xn2) - m2*xp1;
        float x2 = u2*q[5];
        float x1 = (u1 - q[4]*x2)*q[3];
        float x0 = (u0 - q[1]*x1 - q[2]*x2)*q[0];
        float* op = ox + obase + ostep*k;
        op[0] = x0; op[1] = x1; op[2] = x2;
        xp1 = xn1; xn0 = x0; xn1 = x1; xn2 = x2;
    }

    // ---- coalesced store-out ----
    __syncthreads();
    {
        const float4* s = (const float4*)s_co;
        float4* g = (float4*)(out + blk * 90);
        for (int k = tid; k < E_*90/4; k += TPB) g[k] = s[k];
    }
}

extern "C" void kernel_launch(void* const* d_in, const int* in_sizes, int n_in,
                              void* d_out, int out_size) {
    const float* coeffs = (const float*)d_in[0];
    const float* rhs    = (const float*)d_in[1];
    const float* iv_rhs = (const float*)d_in[2];
    const float* steps  = (const float*)d_in[3];
    float* out = (float*)d_out;

    cudaFuncSetAttribute(ode_babe_kernel,
                         cudaFuncAttributeMaxDynamicSharedMemorySize, SV_BYTES);

    dim3 block(TPB);
    dim3 grid(BS_ / E_);   // 256 blocks >= 148 SMs
    ode_babe_kernel<<<grid, block, SV_BYTES>>>(coeffs, rhs, iv_rhs, steps, out);
}

// round 12
// speedup vs baseline: 1.4404x; 1.0090x over previous
#include <cuda_runtime.h>

#define BS_  8192
#define NS_  30
#define KH_  14      // each side eliminates 14 blocks; interface blocks 14,15
#define E_   32      // elements per block
#define TPB  64      // lane 2k = top half of elem k, lane 2k+1 = bottom half

#define SV_V 5       // float4 vectors per record (20 floats, 80B stride)
#define SV_BYTES (SV_V * 16 * KH_ * TPB)   // 71680 B dynamic smem

// Streaming block elimination step; factor record -> shared memory as float4.
#define ELIM_STEP(SVIDX) do {                                                    \
    float il00 = rsqrtf(D000);                                                   \
    float l10 = D010*il00, l20 = D020*il00;                                      \
    float il11 = rsqrtf(D011 - l10*l10);                                         \
    float l21 = (D021 - l20*l10)*il11;                                           \
    float il22 = rsqrtf(D022 - l20*l20 - l21*l21);                               \
    float w0,w1,w2;                                                              \
    w0 = A00*il00; w1 = (A01 - w0*l10)*il11; w2 = (A02 - w0*l20 - w1*l21)*il22;  \
    A00=w0; A01=w1; A02=w2;                                                      \
    w0 = A10*il00; w1 = (A11 - w0*l10)*il11; w2 = (A12 - w0*l20 - w1*l21)*il22;  \
    A10=w0; A11=w1; A12=w2;                                                      \
    w0 = A20*il00; w1 = (A21 - w0*l10)*il11; w2 = (A22 - w0*l20 - w1*l21)*il22;  \
    A20=w0; A21=w1; A22=w2;                                                      \
    float m1 = -il11;                                                            \
    float m2 = il11*l21*il22;                                                    \
    float y0 = r00*il00;                                                         \
    float y1 = (r01 - y0*l10)*il11;                                              \
    float y2 = (r02 - y0*l20 - y1*l21)*il22;                                     \
    r10 -= A00*y0 + A01*y1 + A02*y2;                                             \
    r11 -= A10*y0 + A11*y1 + A12*y2;                                             \
    r12 -= A20*y0 + A21*y1 + A22*y2;                                             \
    r21 -= m1*y1 + m2*y2;                                                        \
    D100 -= A00*A00 + A01*A01 + A02*A02;                                         \
    D110 -= A10*A00 + A11*A01 + A12*A02;                                         \
    D120 -= A20*A00 + A21*A01 + A22*A02;                                         \
    D111 -= A10*A10 + A11*A11 + A12*A12;                                         \
    D121 -= A20*A10 + A21*A11 + A22*A12;                                         \
    D122 -= A20*A20 + A21*A21 + A22*A22;                                         \
    B10 -= m1*A01 + m2*A02;                                                      \
    B11 -= m1*A11 + m2*A12;                                                      \
    B12 -= m1*A21 + m2*A22;                                                      \
    D211 -= m1*m1 + m2*m2;                                                       \
    {                                                                            \
        float4* sp = ((float4*)s_sv) + ((SVIDX)*TPB + tid)*SV_V;                 \
        sp[0] = make_float4(il00, l10, l20, il11);                               \
        sp[1] = make_float4(l21, il22, A00, A01);                                \
        sp[2] = make_float4(A02, A10, A11, A12);                                 \
        sp[3] = make_float4(A20, A21, A22, y0);                                  \
        sp[4] = make_float4(y1, y2, 0.f, 0.f);                                   \
    }                                                                            \
    D000=D100; D010=D110; D020=D120; D011=D111; D021=D121; D022=D122;            \
    D100=0; D110=0; D120=0; D111=D211; D121=0; D122=0; D211=0;                   \
    A00=0; A01=0; A02=0; A10=B10; A11=B11; A12=B12; A20=0; A21=0; A22=0;         \
    B10=0; B11=0; B12=0;                                                         \
    r00=r10; r01=r11; r02=r12;                                                   \
    r10=0; r11=r21; r12=0; r21=0;                                                \
} while(0)

__global__ __launch_bounds__(TPB)
void ode_babe_kernel(const float* __restrict__ coeffs,
                     const float* __restrict__ rhs,
                     const float* __restrict__ ivr,
                     const float* __restrict__ steps,
                     float* __restrict__ out)
{
    __shared__ float s_co[E_ * 90];   // coeffs in; reused for x out
    __shared__ float s_rr[E_ * 30];
    __shared__ float s_st[E_ * 29];
    __shared__ float s_iv[E_ * 4];
    extern __shared__ float s_sv[];   // factor records (dynamic, float4-packed)

    const int tid = threadIdx.x;
    const size_t blk = (size_t)blockIdx.x * E_;

    // ---- coalesced staging ----
    {
        const float4* g = (const float4*)(coeffs + blk * 90);
        float4* s = (float4*)s_co;
        for (int k = tid; k < E_*90/4; k += TPB) s[k] = g[k];
    }
    {
        const float4* g = (const float4*)(rhs + blk * 30);
        float4* s = (float4*)s_rr;
        for (int k = tid; k < E_*30/4; k += TPB) s[k] = g[k];
    }
    {
        const float4* g = (const float4*)(steps + blk * 29);
        float4* s = (float4*)s_st;
        for (int k = tid; k < E_*29/4; k += TPB) s[k] = g[k];
    }
    {
        const float4* g = (const float4*)(ivr + blk * 4);
        float4* s = (float4*)s_iv;
        for (int k = tid; k < E_*4/4; k += TPB) s[k] = g[k];
    }
    __syncthreads();

    const int  e   = tid >> 1;          // element index within block
    const bool top = (tid & 1) == 0;    // even lane = top, odd = bottom

    const float* cc  = s_co + e * 90;
    const float* rrp = s_rr + e * 30;
    const float* stp = s_st + e * 29;

    // direction constants (uniform code path)
    const float sgn   = top ? 1.f : -1.f;
    const int   cbase = top ? 0 : 87;
    const int   cstep = top ? 3 : -3;
    const int   rbase = top ? 0 : 29;
    const int   rstep = top ? 1 : -1;
    const int   hbase = top ? 0 : 28;
    const int   hstep = top ? 1 : -1;

    const float one_t = top ? 1.f : 0.f;
    const float iva0 = top ? s_iv[e*4+0] : 0.f;
    const float iva1 = top ? s_iv[e*4+1] : 0.f;
    const float iva2 = top ? s_iv[e*4+2] : 0.f;
    const float iva3 = top ? s_iv[e*4+3] : 0.f;

    float D000=0,D010=0,D020=0,D011=0,D021=0,D022=0;
    float D100=0,D110=0,D120=0,D111=0,D121=0,D122=0;
    float D211=0;
    float A00=0,A01=0,A02=0,A10=0,A11=0,A12=0,A20=0,A21=0,A22=0;
    float B10=0,B11=0,B12=0;
    float r00=0,r01=0,r02=0, r10=0,r11=0,r12=0, r21=0;

    #pragma unroll
    for (int s = 0; s < KH_; s++) {
        const float* cb = cc + cbase + cstep*s;
        float c0=cb[0], c1=cb[1], c2=cb[2];
        float rv = rrp[rbase + rstep*s];

        D000 += c0*c0; D010 += c1*c0; D020 += c2*c0;
        D011 += c1*c1; D021 += c2*c1; D022 += c2*c2;
        r00 += c0*rv; r01 += c1*rv; r02 += c2*rv;
        if (s == 0) { D000 += one_t; D011 += one_t; r00 += iva0; r01 += iva1; }
        if (s == 1) { D000 += one_t; D011 += one_t; r00 += iva2; r01 += iva3; }

        float h = sgn * stp[hbase + hstep*s];
        float h2 = h*h, h3 = h2*h, h4 = h2*h2;
        D000 += 2.f;       D010 += h;          D020 += 0.5f*h2;
        D011 += 3.f*h2;    D021 += 1.5f*h3;    D022 += 1.25f*h4;
        A00  += -2.f;      A01  += -h;         A02  += -0.5f*h2;
        A10  += h;         A11  += -2.f*h2;    A12  += -h3;
        A20  += -0.5f*h2;  A21  += h3;
        D100 += 2.f;       D110 += -h;         D120 += 0.5f*h2;
        D111 += 3.f*h2;    D121 += -1.5f*h3;   D122 += 1.25f*h4;

        float cp = h + sgn * stp[hbase + hstep*(s+1)];
        D011 += 1.f;  A21 += cp;
        D122 += cp*cp; B12 += -cp; D211 += 1.f;

        ELIM_STEP(s);
    }

    // ---- interface carry exchange via warp shuffle (partner = lane^1) ----
    float te[14], be[14];
    {
        float mine[14] = { D000, D010, D020, D011, D021, D022, D111,
                           A10, A11, A12, r00, r01, r02, r11 };
        #pragma unroll
        for (int i = 0; i < 14; i++) {
            float theirs = __shfl_xor_sync(0xffffffffu, mine[i], 1);
            te[i] = top ? mine[i] : theirs;
            be[i] = top ? theirs  : mine[i];
        }
    }

    // ---- interface: 6x6 SPD solve for x_14, x_15 (computed by both lanes) ----
    float x10_, x11_, x12_, x20_, x21_, x22_;
    {
        float h = stp[KH_];
        float h2 = h*h, h3 = h2*h, h4 = h2*h2;
        float cK0=cc[3*KH_], cK1=cc[3*KH_+1], cK2=cc[3*KH_+2];
        float cL0=cc[3*KH_+3], cL1=cc[3*KH_+4], cL2=cc[3*KH_+5];
        float rvK = rrp[KH_], rvL = rrp[KH_+1];

        float d00 = te[0] + cK0*cK0 + 2.f;
        float d10 = te[1] + cK1*cK0 + h;
        float d20 = te[2] + cK2*cK0 + 0.5f*h2;
        float d11 = te[3] + cK1*cK1 + 3.f*h2 + be[6];
        float d21 = te[4] + cK2*cK1 + 1.5f*h3;
        float d22 = te[5] + cK2*cK2 + 1.25f*h4;
        float e00 = be[0] + cL0*cL0 + 2.f;
        float e10 = be[1] + cL1*cL0 - h;
        float e20 = be[2] + cL2*cL0 + 0.5f*h2;
        float e11 = be[3] + cL1*cL1 + 3.f*h2 + te[6];
        float e21 = be[4] + cL2*cL1 - 1.5f*h3;
        float e22 = be[5] + cL2*cL2 + 1.25f*h4;
        float a00 = -2.f;
        float a01 = -h        + be[7];
        float a02 = -0.5f*h2;
        float a10 =  h        + te[7];
        float a11 = -2.f*h2   + te[8] + be[8];
        float a12 = -h3       + te[9];
        float a20 = -0.5f*h2;
        float a21 =  h3       + be[9];
        float a22 = 0.f;
        float rk0 = te[10] + cK0*rvK;
        float rk1 = te[11] + cK1*rvK + be[13];
        float rk2 = te[12] + cK2*rvK;
        float rl0 = be[10] + cL0*rvL;
        float rl1 = be[11] + cL1*rvL + te[13];
        float rl2 = be[12] + cL2*rvL;

        float il00 = rsqrtf(d00);
        float l10 = d10*il00, l20 = d20*il00;
        float il11 = rsqrtf(d11 - l10*l10);
        float l21 = (d21 - l20*l10)*il11;
        float il22 = rsqrtf(d22 - l20*l20 - l21*l21);
        float w00 = a00*il00, w01 = (a01 - w00*l10)*il11, w02 = (a02 - w00*l20 - w01*l21)*il22;
        float w10 = a10*il00, w11 = (a11 - w10*l10)*il11, w12 = (a12 - w10*l20 - w11*l21)*il22;
        float w20 = a20*il00, w21 = (a21 - w20*l10)*il11, w22 = (a22 - w20*l20 - w21*l21)*il22;
        float s00 = e00 - (w00*w00 + w01*w01 + w02*w02);
        float s10 = e10 - (w10*w00 + w11*w01 + w12*w02);
        float s20 = e20 - (w20*w00 + w21*w01 + w22*w02);
        float s11 = e11 - (w10*w10 + w11*w11 + w12*w12);
        float s21 = e21 - (w20*w10 + w21*w11 + w22*w12);
        float s22 = e22 - (w20*w20 + w21*w21 + w22*w22);
        float jl00 = rsqrtf(s00);
        float k10 = s10*jl00, k20 = s20*jl00;
        float jl11 = rsqrtf(s11 - k10*k10);
        float k21 = (s21 - k20*k10)*jl11;
        float jl22 = rsqrtf(s22 - k20*k20 - k21*k21);
        float y10 = rk0*il00;
        float y11 = (rk1 - y10*l10)*il11;
        float y12 = (rk2 - y10*l20 - y11*l21)*il22;
        float t0 = rl0 - (w00*y10 + w01*y11 + w02*y12);
        float t1 = rl1 - (w10*y10 + w11*y11 + w12*y12);
        float t2 = rl2 - (w20*y10 + w21*y11 + w22*y12);
        float y20 = t0*jl00;
        float y21 = (t1 - y20*k10)*jl11;
        float y22 = (t2 - y20*k20 - y21*k21)*jl22;
        x22_ = y22*jl22;
        x21_ = (y21 - k21*x22_)*jl11;
        x20_ = (y20 - k10*x21_ - k20*x22_)*jl00;
        float z0 = y10 - (w00*x20_ + w10*x21_ + w20*x22_);
        float z1 = y11 - (w01*x20_ + w11*x21_ + w21*x22_);
        float z2 = y12 - (w02*x20_ + w12*x21_ + w22*x22_);
        x12_ = z2*il22;
        x11_ = (z1 - l21*x12_)*il11;
        x10_ = (z0 - l10*x11_ - l20*x12_)*il00;
    }

    // ---- back substitution (vectorized, prefetched smem factor reads) ----
    float* ox = s_co + e * 90;   // coeffs consumed; reuse as output staging
    if (top) {
        ox[3*KH_+0]=x10_; ox[3*KH_+1]=x11_; ox[3*KH_+2]=x12_;
        ox[3*KH_+3]=x20_; ox[3*KH_+4]=x21_; ox[3*KH_+5]=x22_;
    }
    float xn0 = top ? x10_ : x20_;
    float xn1 = top ? x11_ : x21_;
    float xn2 = top ? x12_ : x22_;
    float xp1 = top ? x21_ : x11_;
    const int obase = top ? 0 : 87;
    const int ostep = top ? 3 : -3;

    const float4* sb = (const float4*)s_sv;
    float4 p0, p1, p2, p3, p4;
    {
        const float4* sp = sb + ((KH_-1)*TPB + tid)*SV_V;
        p0 = sp[0]; p1 = sp[1]; p2 = sp[2]; p3 = sp[3]; p4 = sp[4];
    }

    #pragma unroll
    for (int k = KH_-1; k >= 0; k--) {
        float4 q0 = p0, q1 = p1, q2 = p2, q3 = p3, q4 = p4;
        if (k > 0) {   // prefetch next record off the chain
            const float4* sp = sb + ((k-1)*TPB + tid)*SV_V;
            p0 = sp[0]; p1 = sp[1]; p2 = sp[2]; p3 = sp[3]; p4 = sp[4];
        }
        // fields: q0=(il00,l10,l20,il11) q1=(l21,il22,A00,A01)
        //         q2=(A02,A10,A11,A12)  q3=(A20,A21,A22,y0)  q4=(y1,y2,-,-)
        float m2 = q0.w * q1.x * q1.y;     // il11*l21*il22
        float u0 = q3.w - (q1.z*xn0 + q2.y*xn1 + q3.x*xn2);
        float u1 = q4.x - (q1.w*xn0 + q2.z*xn1 + q3.y*xn2) + q0.w*xp1;
        float u2 = q4.y - (q2.x*xn0 + q2.w*xn1 + q3.z*xn2) - m2*xp1;
        float x2 = u2*q1.y;
        float x1 = (u1 - q1.x*x2)*q0.w;
        float x0 = (u0 - q0.y*x1 - q0.z*x2)*q0.x;
        float* op = ox + obase + ostep*k;
        op[0] = x0; op[1] = x1; op[2] = x2;
        xp1 = xn1; xn0 = x0; xn1 = x1; xn2 = x2;
    }

    // ---- coalesced store-out ----
    __syncthreads();
    {
        const float4* s = (const float4*)s_co;
        float4* g = (float4*)(out + blk * 90);
        for (int k = tid; k < E_*90/4; k += TPB) g[k] = s[k];
    }
}

extern "C" void kernel_launch(void* const* d_in, const int* in_sizes, int n_in,
                              void* d_out, int out_size) {
    const float* coeffs = (const float*)d_in[0];
    const float* rhs    = (const float*)d_in[1];
    const float* iv_rhs = (const float*)d_in[2];
    const float* steps  = (const float*)d_in[3];
    float* out = (float*)d_out;

    cudaFuncSetAttribute(ode_babe_kernel,
                         cudaFuncAttributeMaxDynamicSharedMemorySize, SV_BYTES);

    dim3 block(TPB);
    dim3 grid(BS_ / E_);   // 256 blocks
    ode_babe_kernel<<<grid, block, SV_BYTES>>>(coeffs, rhs, iv_rhs, steps, out);
}